// round 10
// baseline (speedup 1.0000x reference)
#include <cuda_runtime.h>
#include <cuda_bf16.h>
#include <math.h>

#define Bn 8
#define Tn 512
#define Cn 8
#define Fn 257
#define An 320
#define BF (Bn*Fn)   // 2056
#define FT 32        // f per psd block
#define TS 4         // t splits
#define TL 128       // t per split
#define TC 16        // t chunk staged in smem

// ---------------- scratch (static device globals; no allocation) ----------------
__device__ float  g_part[(size_t)TS*BF*36*4];     // unnormalized pair partials
__device__ float  g_msum_part[(size_t)TS*BF*2];   // mask-weight sums per split
__device__ float2 g_psd_s[(size_t)BF*Cn*Cn];      // (B,F,C,C)
__device__ float2 g_psd_n[(size_t)BF*Cn*Cn];
__device__ float  g_eval[Bn*Cn];
__device__ float2 g_ws[(size_t)BF*Cn];            // (B,F,C)

// Hermitian pair tables (c<=e), 36 pairs
__constant__ unsigned char cP[36] = {0,0,0,0,0,0,0,0, 1,1,1,1,1,1,1, 2,2,2,2,2,2,
                                     3,3,3,3,3, 4,4,4,4, 5,5,5, 6,6, 7};
__constant__ unsigned char cE[36] = {0,1,2,3,4,5,6,7, 1,2,3,4,5,6,7, 2,3,4,5,6,7,
                                     3,4,5,6,7, 4,5,6,7, 5,6,7, 6,7, 7};
__device__ static constexpr int kP[36] = {0,0,0,0,0,0,0,0, 1,1,1,1,1,1,1, 2,2,2,2,2,2,
                                          3,3,3,3,3, 4,4,4,4, 5,5,5, 6,6, 7};
__device__ static constexpr int kE[36] = {0,1,2,3,4,5,6,7, 1,2,3,4,5,6,7, 2,3,4,5,6,7,
                                          3,4,5,6,7, 4,5,6,7, 5,6,7, 6,7, 7};

// ---------------- PSD partial kernel smem ----------------
struct PsdSmem {
    float m0[FT][TL + 1];                 // c-mean speech weights, [f][t] rows
    float m1[FT][TL + 1];
    union {
        float2 xt[TC][Cn][FT];            // staged x chunk, [t][c][f]
        float  stage[4][FT][36];          // cross-warp pair reduction
    } u;
};
#define PSD_SMEM_BYTES sizeof(PsdSmem)

template<int G>
__device__ __forceinline__ void psd_chunk(
    const PsdSmem* __restrict__ S, int lane, int st, int tb,
    float (&asr)[9], float (&asi)[9], float (&anr)[9], float (&ani)[9])
{
    #pragma unroll
    for (int tl = st; tl < TC; tl += 2) {
        float w0 = S->m0[lane][tb + tl];
        float w1 = S->m1[lane][tb + tl];
        float2 xv[8];
        #pragma unroll
        for (int c = 0; c < 8; c++) xv[c] = S->u.xt[tl][c][lane];
        #pragma unroll
        for (int p = 0; p < 9; p++) {
            const int c = kP[G*9 + p];
            const int e = kE[G*9 + p];
            float pr = xv[c].x*xv[e].x + xv[c].y*xv[e].y;
            float pi = xv[c].y*xv[e].x - xv[c].x*xv[e].y;
            asr[p] += w0*pr; asi[p] += w0*pi;
            anr[p] += w1*pr; ani[p] += w1*pi;
        }
    }
}

// grid (9 ftiles, 4 tsplits, 8 b), 256 threads
__global__ __launch_bounds__(256) void k_psd_part(
    const float* __restrict__ dr, const float* __restrict__ di,
    const float* __restrict__ ms, const float* __restrict__ mn)
{
    extern __shared__ char raw[];
    PsdSmem* S = (PsdSmem*)raw;
    int ftile = blockIdx.x, ts = blockIdx.y, b = blockIdx.z;
    int f0 = ftile * FT;
    int nf = Fn - f0; if (nf > FT) nf = FT;
    int t0 = ts * TL;
    int tid = threadIdx.x;
    int w = tid >> 5, lane = tid & 31;

    // ---- Phase A: mask c-means into smem, plus per-f t-sums ----
    #pragma unroll
    for (int ff = 0; ff < 4; ff++) {
        int fw = w*4 + ff;
        float s0[4] = {0.f,0.f,0.f,0.f}, s1[4] = {0.f,0.f,0.f,0.f};
        if (fw < nf) {
            size_t base = ((size_t)(b*Fn + f0 + fw))*Cn*Tn + t0 + lane;
            #pragma unroll
            for (int c = 0; c < 8; c++) {
                #pragma unroll
                for (int j = 0; j < 4; j++) {
                    s0[j] += ms[base + (size_t)c*Tn + 32*j];
                    s1[j] += mn[base + (size_t)c*Tn + 32*j];
                }
            }
        }
        float tot0 = 0.f, tot1 = 0.f;
        #pragma unroll
        for (int j = 0; j < 4; j++) {
            S->m0[fw][lane + 32*j] = s0[j] * 0.125f;
            S->m1[fw][lane + 32*j] = s1[j] * 0.125f;
            tot0 += s0[j]; tot1 += s1[j];
        }
        #pragma unroll
        for (int o = 16; o; o >>= 1) {
            tot0 += __shfl_xor_sync(0xffffffffu, tot0, o);
            tot1 += __shfl_xor_sync(0xffffffffu, tot1, o);
        }
        if (lane == 0 && fw < nf) {
            size_t mi = ((size_t)ts*BF + b*Fn + f0 + fw)*2;
            g_msum_part[mi + 0] = tot0 * 0.125f;
            g_msum_part[mi + 1] = tot1 * 0.125f;
        }
    }
    __syncthreads();

    // ---- Phase B: stage x chunks (fully coalesced) + accumulate pairs ----
    int G4 = w >> 1, st = w & 1;
    bool fok = (f0 + lane < Fn);
    float asr[9], asi[9], anr[9], ani[9];
    #pragma unroll
    for (int p = 0; p < 9; p++) { asr[p]=0.f; asi[p]=0.f; anr[p]=0.f; ani[p]=0.f; }

    for (int ch = 0; ch < TL/TC; ch++) {
        int tb = ch * TC;
        #pragma unroll
        for (int it = 0; it < TC; it++) {
            float vr = 0.f, vi = 0.f;
            if (fok) {
                size_t ga = ((size_t)((b*Tn + t0 + tb + it))*Cn + w)*Fn + f0 + lane;
                vr = dr[ga]; vi = di[ga];
            }
            S->u.xt[it][w][lane] = make_float2(vr, vi);
        }
        __syncthreads();
        if      (G4 == 0) psd_chunk<0>(S, lane, st, tb, asr, asi, anr, ani);
        else if (G4 == 1) psd_chunk<1>(S, lane, st, tb, asr, asi, anr, ani);
        else if (G4 == 2) psd_chunk<2>(S, lane, st, tb, asr, asi, anr, ani);
        else              psd_chunk<3>(S, lane, st, tb, asr, asi, anr, ani);
        __syncthreads();
    }

    // ---- reduce st pairs across the two warps of each group, write partials ----
    if (st == 1) {
        #pragma unroll
        for (int p = 0; p < 9; p++) {
            S->u.stage[G4][lane][p*4 + 0] = asr[p];
            S->u.stage[G4][lane][p*4 + 1] = asi[p];
            S->u.stage[G4][lane][p*4 + 2] = anr[p];
            S->u.stage[G4][lane][p*4 + 3] = ani[p];
        }
    }
    __syncthreads();
    if (st == 0 && fok) {
        size_t gp = (((size_t)ts*BF + b*Fn + f0 + lane)*36 + G4*9)*4;
        #pragma unroll
        for (int p = 0; p < 9; p++) {
            g_part[gp + p*4 + 0] = asr[p] + S->u.stage[G4][lane][p*4 + 0];
            g_part[gp + p*4 + 1] = asi[p] + S->u.stage[G4][lane][p*4 + 1];
            g_part[gp + p*4 + 2] = anr[p] + S->u.stage[G4][lane][p*4 + 2];
            g_part[gp + p*4 + 3] = ani[p] + S->u.stage[G4][lane][p*4 + 3];
        }
    }
}

// ---------------- PSD finalize: sum splits, normalize, emit matrices -------------
// grid 257, block 288 = 8 bf x 36 pairs
__global__ __launch_bounds__(288) void k_psd_final() {
    int tid = threadIdx.x;
    int bf = blockIdx.x * 8 + tid / 36;
    int p = tid % 36;
    float ms0 = 0.f, ms1 = 0.f, a0 = 0.f, a1 = 0.f, a2 = 0.f, a3 = 0.f;
    #pragma unroll
    for (int ts = 0; ts < TS; ts++) {
        size_t mi = ((size_t)ts*BF + bf)*2;
        ms0 += g_msum_part[mi + 0];
        ms1 += g_msum_part[mi + 1];
        size_t gp = (((size_t)ts*BF + bf)*36 + p)*4;
        a0 += g_part[gp + 0]; a1 += g_part[gp + 1];
        a2 += g_part[gp + 2]; a3 += g_part[gp + 3];
    }
    float inv0 = 1.f / (ms0 + 1e-15f);
    float inv1 = 1.f / (ms1 + 1e-15f);
    int c = cP[p], e = cE[p];
    size_t base = (size_t)bf * 64;
    g_psd_s[base + c*8 + e] = make_float2(a0*inv0,  a1*inv0);
    g_psd_s[base + e*8 + c] = make_float2(a0*inv0, -a1*inv0);
    g_psd_n[base + c*8 + e] = make_float2(a2*inv1,  a3*inv1);
    g_psd_n[base + e*8 + c] = make_float2(a2*inv1, -a3*inv1);
}

// ---------------- attention MLP -> e[b,c]. 64 blocks x 320 threads --------
__global__ __launch_bounds__(An) void k_att(const float* __restrict__ mlp_w,
                                            const float* __restrict__ mlp_b,
                                            const float* __restrict__ gvw,
                                            const float* __restrict__ gvb) {
    __shared__ float feat[Fn];
    __shared__ float red[10];
    int b = blockIdx.x >> 3, c = blockIdx.x & 7;
    int tid = threadIdx.x;

    if (tid < Fn) {
        const float2* p = g_psd_s + ((size_t)(b*Fn + tid))*64 + c*8;
        float sr = 0.f, si = 0.f;
        #pragma unroll
        for (int e = 0; e < 8; e++) {
            if (e != c) { sr += p[e].x; si += p[e].y; }
        }
        feat[tid] = sqrtf(sr*sr + si*si) * (1.0f/7.0f);
    }
    __syncthreads();

    float dot = 0.f;
    for (int f = 0; f < Fn; f++) dot += feat[f] * mlp_w[f*An + tid];
    float h = tanhf(dot + mlp_b[tid]);
    float part = h * gvw[tid];

    #pragma unroll
    for (int o = 16; o; o >>= 1) part += __shfl_xor_sync(0xffffffffu, part, o);
    int w = tid >> 5, lane = tid & 31;
    if (lane == 0) red[w] = part;
    __syncthreads();
    if (tid == 0) {
        float s = 0.f;
        #pragma unroll
        for (int k = 0; k < 10; k++) s += red[k];
        g_eval[blockIdx.x] = s + gvb[0];
    }
}

// ---------------- MVDR solve (softmax inlined), warp-synchronous fp32 -------------
__global__ __launch_bounds__(256) void k_mvdr() {
    const unsigned FULL = 0xffffffffu;
    __shared__ float u_sm[8][8];
    int w = threadIdx.x >> 5;
    int bf = blockIdx.x * 8 + w;          // grid = 257
    int lane = threadIdx.x & 31;
    int i = lane >> 2;                    // row 0..7
    int q = lane & 3;                     // col group
    int b = bf / Fn;

    // inline softmax over channels for this bf's batch
    {
        int c8 = lane & 7;
        float v = 2.0f * g_eval[b*8 + c8];
        float mx = v;
        #pragma unroll
        for (int o = 1; o < 8; o <<= 1) mx = fmaxf(mx, __shfl_xor_sync(FULL, mx, o));
        float ex = expf(v - mx);
        float s = ex;
        #pragma unroll
        for (int o = 1; o < 8; o <<= 1) s += __shfl_xor_sync(FULL, s, o);
        if (lane < 8) u_sm[w][lane] = ex / s;
        __syncwarp();
    }

    float ar[4], ai[4];
    #pragma unroll
    for (int m = 0; m < 4; m++) {
        int j = q*4 + m;
        float2 v = (j < 8) ? g_psd_n[(size_t)bf*64 + i*8 + j]
                           : g_psd_s[(size_t)bf*64 + i*8 + (j - 8)];
        ar[m] = v.x; ai[m] = v.y;
    }

    #pragma unroll
    for (int k = 0; k < 8; k++) {
        int psrc = (k << 2) | (k >> 2);
        float pvr = __shfl_sync(FULL, ar[k & 3], psrc);
        float pvi = __shfl_sync(FULL, ai[k & 3], psrc);
        float dd = 1.f / (pvr*pvr + pvi*pvi);
        float qr = pvr*dd, qi = -pvi*dd;
        if (i == k) {
            #pragma unroll
            for (int m = 0; m < 4; m++) {
                float trv = ar[m]*qr - ai[m]*qi;
                ai[m] = ar[m]*qi + ai[m]*qr;
                ar[m] = trv;
            }
        }
        float gr[4], gi[4];
        int rsrc = (k << 2) | q;
        #pragma unroll
        for (int m = 0; m < 4; m++) {
            gr[m] = __shfl_sync(FULL, ar[m], rsrc);
            gi[m] = __shfl_sync(FULL, ai[m], rsrc);
        }
        int fsrc = (i << 2) | (k >> 2);
        float fr = __shfl_sync(FULL, ar[k & 3], fsrc);
        float fi = __shfl_sync(FULL, ai[k & 3], fsrc);
        if (i != k) {
            #pragma unroll
            for (int m = 0; m < 4; m++) {
                ar[m] -= fr*gr[m] - fi*gi[m];
                ai[m] -= fr*gi[m] + fi*gr[m];
            }
        }
    }

    float tr_r = 0.f, tr_i = 0.f;
    if (q == ((8 + i) >> 2)) {
        int m = (8 + i) & 3;
        tr_r = ar[m]; tr_i = ai[m];
    }
    #pragma unroll
    for (int o = 16; o; o >>= 1) {
        tr_r += __shfl_xor_sync(FULL, tr_r, o);
        tr_i += __shfl_xor_sync(FULL, tr_i, o);
    }
    tr_r += 1e-15f;

    float sr = 0.f, si = 0.f;
    if (q >= 2) {
        #pragma unroll
        for (int m = 0; m < 4; m++) {
            int c = (q - 2)*4 + m;
            float uu = u_sm[w][c];
            sr += ar[m]*uu; si += ai[m]*uu;
        }
    }
    sr += __shfl_xor_sync(FULL, sr, 1); si += __shfl_xor_sync(FULL, si, 1);
    sr += __shfl_xor_sync(FULL, sr, 2); si += __shfl_xor_sync(FULL, si, 2);
    if (q == 0) {
        float dd = 1.f / (tr_r*tr_r + tr_i*tr_i);
        float wr = (sr*tr_r + si*tr_i)*dd;
        float wi = (si*tr_r - sr*tr_i)*dd;
        g_ws[(size_t)bf*8 + i] = make_float2(wr, wi);
    }
}

// ---------------- beamforming -> output (B,T,F,2) ----------------
#define TCH 8
__global__ __launch_bounds__(288) void k_beam(const float* __restrict__ dr,
                                              const float* __restrict__ di,
                                              float2* __restrict__ out) {
    int blk = blockIdx.x;
    int b  = blk / (Tn / TCH);
    int t0 = (blk % (Tn / TCH)) * TCH;
    int f = threadIdx.x;
    if (f >= Fn) return;

    float2 wv[8];
    const float2* wp = g_ws + ((size_t)(b*Fn + f))*8;
    #pragma unroll
    for (int c = 0; c < 8; c++) wv[c] = wp[c];

    #pragma unroll
    for (int tt = 0; tt < TCH; tt++) {
        int t = t0 + tt;
        size_t base = ((size_t)(b*Tn + t))*Cn*Fn + f;
        float accr = 0.f, acci = 0.f;
        #pragma unroll
        for (int c = 0; c < 8; c++) {
            float xr = dr[base + (size_t)c*Fn];
            float xi = di[base + (size_t)c*Fn];
            accr += wv[c].x*xr + wv[c].y*xi;
            acci += wv[c].x*xi - wv[c].y*xr;
        }
        out[(size_t)(b*Tn + t)*Fn + f] = make_float2(accr, acci);
    }
}

// ---------------- launcher ----------------
extern "C" void kernel_launch(void* const* d_in, const int* in_sizes, int n_in,
                              void* d_out, int out_size) {
    const float* dr    = (const float*)d_in[0];
    const float* di    = (const float*)d_in[1];
    const float* ms    = (const float*)d_in[2];
    const float* mn    = (const float*)d_in[3];
    const float* mlp_w = (const float*)d_in[4];
    const float* mlp_b = (const float*)d_in[5];
    const float* gvw   = (const float*)d_in[6];
    const float* gvb   = (const float*)d_in[7];
    (void)in_sizes; (void)n_in; (void)out_size;

    static bool attr_set = false;
    if (!attr_set) {
        cudaFuncSetAttribute(k_psd_part, cudaFuncAttributeMaxDynamicSharedMemorySize,
                             (int)PSD_SMEM_BYTES);
        attr_set = true;
    }

    k_psd_part<<<dim3((Fn + FT - 1)/FT, TS, Bn), 256, PSD_SMEM_BYTES>>>(dr, di, ms, mn);
    k_psd_final<<<257, 288>>>();
    k_att<<<Bn*Cn, An>>>(mlp_w, mlp_b, gvw, gvb);
    k_mvdr<<<257, 256>>>();
    k_beam<<<Bn*(Tn/TCH), 288>>>(dr, di, (float2*)d_out);
}

// round 11
// speedup vs baseline: 1.2608x; 1.2608x over previous
#include <cuda_runtime.h>
#include <cuda_bf16.h>
#include <math.h>

#define Bn 8
#define Tn 512
#define Cn 8
#define Fn 257
#define An 320
#define BF (Bn*Fn)   // 2056
#define FT 32        // f per psd block
#define TS 4         // t splits
#define TL 128       // t per split
#define TC 8         // t chunk staged in smem (register-prefetch pipelined)
#define NCH (TL/TC)  // 16 chunks

// ---------------- scratch (static device globals; no allocation) ----------------
__device__ float  g_part[(size_t)TS*BF*36*4];     // unnormalized pair partials
__device__ float  g_msum_part[(size_t)TS*BF*2];   // mask-weight sums per split
__device__ float2 g_psd_s[(size_t)BF*Cn*Cn];      // (B,F,C,C)
__device__ float2 g_psd_n[(size_t)BF*Cn*Cn];
__device__ float  g_eval[Bn*Cn];
__device__ float2 g_ws[(size_t)BF*Cn];            // (B,F,C)

// Hermitian pair tables (c<=e), 36 pairs
__constant__ unsigned char cP[36] = {0,0,0,0,0,0,0,0, 1,1,1,1,1,1,1, 2,2,2,2,2,2,
                                     3,3,3,3,3, 4,4,4,4, 5,5,5, 6,6, 7};
__constant__ unsigned char cE[36] = {0,1,2,3,4,5,6,7, 1,2,3,4,5,6,7, 2,3,4,5,6,7,
                                     3,4,5,6,7, 4,5,6,7, 5,6,7, 6,7, 7};
__device__ static constexpr int kP[36] = {0,0,0,0,0,0,0,0, 1,1,1,1,1,1,1, 2,2,2,2,2,2,
                                          3,3,3,3,3, 4,4,4,4, 5,5,5, 6,6, 7};
__device__ static constexpr int kE[36] = {0,1,2,3,4,5,6,7, 1,2,3,4,5,6,7, 2,3,4,5,6,7,
                                          3,4,5,6,7, 4,5,6,7, 5,6,7, 6,7, 7};

// ---------------- PSD partial kernel smem ----------------
struct PsdSmem {
    float m0[FT][TL + 1];                 // c-mean speech weights, [f][t] rows
    float m1[FT][TL + 1];
    union {
        float2 xt[TC][Cn][FT];            // staged x chunk, [t][c][f] (16 KB)
        float  stage[4][FT][36];          // cross-warp pair reduction (18.4 KB)
    } u;
};
#define PSD_SMEM_BYTES sizeof(PsdSmem)    // ~51.5 KB -> 4 blocks/SM

template<int G>
__device__ __forceinline__ void psd_chunk(
    const PsdSmem* __restrict__ S, int lane, int st, int tb,
    float (&asr)[9], float (&asi)[9], float (&anr)[9], float (&ani)[9])
{
    #pragma unroll
    for (int tl = st; tl < TC; tl += 2) {
        float w0 = S->m0[lane][tb + tl];
        float w1 = S->m1[lane][tb + tl];
        float2 xv[8];
        #pragma unroll
        for (int c = 0; c < 8; c++) xv[c] = S->u.xt[tl][c][lane];
        #pragma unroll
        for (int p = 0; p < 9; p++) {
            const int c = kP[G*9 + p];
            const int e = kE[G*9 + p];
            float pr = xv[c].x*xv[e].x + xv[c].y*xv[e].y;
            float pi = xv[c].y*xv[e].x - xv[c].x*xv[e].y;
            asr[p] += w0*pr; asi[p] += w0*pi;
            anr[p] += w1*pr; ani[p] += w1*pi;
        }
    }
}

// grid (9 ftiles, 4 tsplits, 8 b), 256 threads
__global__ __launch_bounds__(256) void k_psd_part(
    const float* __restrict__ dr, const float* __restrict__ di,
    const float* __restrict__ ms, const float* __restrict__ mn)
{
    extern __shared__ char raw[];
    PsdSmem* S = (PsdSmem*)raw;
    int ftile = blockIdx.x, ts = blockIdx.y, b = blockIdx.z;
    int f0 = ftile * FT;
    int nf = Fn - f0; if (nf > FT) nf = FT;
    int t0 = ts * TL;
    int tid = threadIdx.x;
    int w = tid >> 5, lane = tid & 31;

    // ---- Phase A: mask c-means into smem, plus per-f t-sums ----
    #pragma unroll
    for (int ff = 0; ff < 4; ff++) {
        int fw = w*4 + ff;
        float s0[4] = {0.f,0.f,0.f,0.f}, s1[4] = {0.f,0.f,0.f,0.f};
        if (fw < nf) {
            size_t base = ((size_t)(b*Fn + f0 + fw))*Cn*Tn + t0 + lane;
            #pragma unroll
            for (int c = 0; c < 8; c++) {
                #pragma unroll
                for (int j = 0; j < 4; j++) {
                    s0[j] += ms[base + (size_t)c*Tn + 32*j];
                    s1[j] += mn[base + (size_t)c*Tn + 32*j];
                }
            }
        }
        float tot0 = 0.f, tot1 = 0.f;
        #pragma unroll
        for (int j = 0; j < 4; j++) {
            S->m0[fw][lane + 32*j] = s0[j] * 0.125f;
            S->m1[fw][lane + 32*j] = s1[j] * 0.125f;
            tot0 += s0[j]; tot1 += s1[j];
        }
        #pragma unroll
        for (int o = 16; o; o >>= 1) {
            tot0 += __shfl_xor_sync(0xffffffffu, tot0, o);
            tot1 += __shfl_xor_sync(0xffffffffu, tot1, o);
        }
        if (lane == 0 && fw < nf) {
            size_t mi = ((size_t)ts*BF + b*Fn + f0 + fw)*2;
            g_msum_part[mi + 0] = tot0 * 0.125f;
            g_msum_part[mi + 1] = tot1 * 0.125f;
        }
    }
    __syncthreads();

    // ---- Phase B: register-prefetch pipelined staging + pair accumulation ----
    int G4 = w >> 1, st = w & 1;
    bool fok = (f0 + lane < Fn);
    float asr[9], asi[9], anr[9], ani[9];
    #pragma unroll
    for (int p = 0; p < 9; p++) { asr[p]=0.f; asi[p]=0.f; anr[p]=0.f; ani[p]=0.f; }

    // per-thread prefetch registers: chunk rows (it, c=w, f=lane)
    float rr[TC], ri[TC];
    {   // prefetch chunk 0
        #pragma unroll
        for (int it = 0; it < TC; it++) {
            rr[it] = 0.f; ri[it] = 0.f;
            if (fok) {
                size_t ga = ((size_t)((b*Tn + t0 + it))*Cn + w)*Fn + f0 + lane;
                rr[it] = dr[ga]; ri[it] = di[ga];
            }
        }
    }

    for (int ch = 0; ch < NCH; ch++) {
        int tb = ch * TC;
        // store prefetched regs to smem
        #pragma unroll
        for (int it = 0; it < TC; it++)
            S->u.xt[it][w][lane] = make_float2(rr[it], ri[it]);
        __syncthreads();

        // issue next chunk's LDGs; latency overlaps the compute below
        if (ch + 1 < NCH) {
            int tbn = (ch + 1) * TC;
            #pragma unroll
            for (int it = 0; it < TC; it++) {
                rr[it] = 0.f; ri[it] = 0.f;
                if (fok) {
                    size_t ga = ((size_t)((b*Tn + t0 + tbn + it))*Cn + w)*Fn + f0 + lane;
                    rr[it] = dr[ga]; ri[it] = di[ga];
                }
            }
        }

        if      (G4 == 0) psd_chunk<0>(S, lane, st, tb, asr, asi, anr, ani);
        else if (G4 == 1) psd_chunk<1>(S, lane, st, tb, asr, asi, anr, ani);
        else if (G4 == 2) psd_chunk<2>(S, lane, st, tb, asr, asi, anr, ani);
        else              psd_chunk<3>(S, lane, st, tb, asr, asi, anr, ani);
        __syncthreads();
    }

    // ---- reduce st pairs across the two warps of each group, write partials ----
    if (st == 1) {
        #pragma unroll
        for (int p = 0; p < 9; p++) {
            S->u.stage[G4][lane][p*4 + 0] = asr[p];
            S->u.stage[G4][lane][p*4 + 1] = asi[p];
            S->u.stage[G4][lane][p*4 + 2] = anr[p];
            S->u.stage[G4][lane][p*4 + 3] = ani[p];
        }
    }
    __syncthreads();
    if (st == 0 && fok) {
        size_t gp = (((size_t)ts*BF + b*Fn + f0 + lane)*36 + G4*9)*4;
        #pragma unroll
        for (int p = 0; p < 9; p++) {
            g_part[gp + p*4 + 0] = asr[p] + S->u.stage[G4][lane][p*4 + 0];
            g_part[gp + p*4 + 1] = asi[p] + S->u.stage[G4][lane][p*4 + 1];
            g_part[gp + p*4 + 2] = anr[p] + S->u.stage[G4][lane][p*4 + 2];
            g_part[gp + p*4 + 3] = ani[p] + S->u.stage[G4][lane][p*4 + 3];
        }
    }
}

// ---------------- PSD finalize: sum splits, normalize, emit matrices -------------
// grid 257, block 288 = 8 bf x 36 pairs
__global__ __launch_bounds__(288) void k_psd_final() {
    int tid = threadIdx.x;
    int bf = blockIdx.x * 8 + tid / 36;
    int p = tid % 36;
    float ms0 = 0.f, ms1 = 0.f, a0 = 0.f, a1 = 0.f, a2 = 0.f, a3 = 0.f;
    #pragma unroll
    for (int ts = 0; ts < TS; ts++) {
        size_t mi = ((size_t)ts*BF + bf)*2;
        ms0 += g_msum_part[mi + 0];
        ms1 += g_msum_part[mi + 1];
        size_t gp = (((size_t)ts*BF + bf)*36 + p)*4;
        a0 += g_part[gp + 0]; a1 += g_part[gp + 1];
        a2 += g_part[gp + 2]; a3 += g_part[gp + 3];
    }
    float inv0 = 1.f / (ms0 + 1e-15f);
    float inv1 = 1.f / (ms1 + 1e-15f);
    int c = cP[p], e = cE[p];
    size_t base = (size_t)bf * 64;
    g_psd_s[base + c*8 + e] = make_float2(a0*inv0,  a1*inv0);
    g_psd_s[base + e*8 + c] = make_float2(a0*inv0, -a1*inv0);
    g_psd_n[base + c*8 + e] = make_float2(a2*inv1,  a3*inv1);
    g_psd_n[base + e*8 + c] = make_float2(a2*inv1, -a3*inv1);
}

// ---------------- attention MLP -> e[b,c]. 64 blocks x 320 threads --------
__global__ __launch_bounds__(An) void k_att(const float* __restrict__ mlp_w,
                                            const float* __restrict__ mlp_b,
                                            const float* __restrict__ gvw,
                                            const float* __restrict__ gvb) {
    __shared__ float feat[Fn];
    __shared__ float red[10];
    int b = blockIdx.x >> 3, c = blockIdx.x & 7;
    int tid = threadIdx.x;

    if (tid < Fn) {
        const float2* p = g_psd_s + ((size_t)(b*Fn + tid))*64 + c*8;
        float sr = 0.f, si = 0.f;
        #pragma unroll
        for (int e = 0; e < 8; e++) {
            if (e != c) { sr += p[e].x; si += p[e].y; }
        }
        feat[tid] = sqrtf(sr*sr + si*si) * (1.0f/7.0f);
    }
    __syncthreads();

    float dot = 0.f;
    for (int f = 0; f < Fn; f++) dot += feat[f] * mlp_w[f*An + tid];
    float h = tanhf(dot + mlp_b[tid]);
    float part = h * gvw[tid];

    #pragma unroll
    for (int o = 16; o; o >>= 1) part += __shfl_xor_sync(0xffffffffu, part, o);
    int w = tid >> 5, lane = tid & 31;
    if (lane == 0) red[w] = part;
    __syncthreads();
    if (tid == 0) {
        float s = 0.f;
        #pragma unroll
        for (int k = 0; k < 10; k++) s += red[k];
        g_eval[blockIdx.x] = s + gvb[0];
    }
}

// ---------------- MVDR solve (softmax inlined), warp-synchronous fp32 -------------
__global__ __launch_bounds__(256) void k_mvdr() {
    const unsigned FULL = 0xffffffffu;
    __shared__ float u_sm[8][8];
    int w = threadIdx.x >> 5;
    int bf = blockIdx.x * 8 + w;          // grid = 257
    int lane = threadIdx.x & 31;
    int i = lane >> 2;                    // row 0..7
    int q = lane & 3;                     // col group
    int b = bf / Fn;

    // inline softmax over channels for this bf's batch
    {
        int c8 = lane & 7;
        float v = 2.0f * g_eval[b*8 + c8];
        float mx = v;
        #pragma unroll
        for (int o = 1; o < 8; o <<= 1) mx = fmaxf(mx, __shfl_xor_sync(FULL, mx, o));
        float ex = expf(v - mx);
        float s = ex;
        #pragma unroll
        for (int o = 1; o < 8; o <<= 1) s += __shfl_xor_sync(FULL, s, o);
        if (lane < 8) u_sm[w][lane] = ex / s;
        __syncwarp();
    }

    float ar[4], ai[4];
    #pragma unroll
    for (int m = 0; m < 4; m++) {
        int j = q*4 + m;
        float2 v = (j < 8) ? g_psd_n[(size_t)bf*64 + i*8 + j]
                           : g_psd_s[(size_t)bf*64 + i*8 + (j - 8)];
        ar[m] = v.x; ai[m] = v.y;
    }

    #pragma unroll
    for (int k = 0; k < 8; k++) {
        int psrc = (k << 2) | (k >> 2);
        float pvr = __shfl_sync(FULL, ar[k & 3], psrc);
        float pvi = __shfl_sync(FULL, ai[k & 3], psrc);
        float dd = 1.f / (pvr*pvr + pvi*pvi);
        float qr = pvr*dd, qi = -pvi*dd;
        if (i == k) {
            #pragma unroll
            for (int m = 0; m < 4; m++) {
                float trv = ar[m]*qr - ai[m]*qi;
                ai[m] = ar[m]*qi + ai[m]*qr;
                ar[m] = trv;
            }
        }
        float gr[4], gi[4];
        int rsrc = (k << 2) | q;
        #pragma unroll
        for (int m = 0; m < 4; m++) {
            gr[m] = __shfl_sync(FULL, ar[m], rsrc);
            gi[m] = __shfl_sync(FULL, ai[m], rsrc);
        }
        int fsrc = (i << 2) | (k >> 2);
        float fr = __shfl_sync(FULL, ar[k & 3], fsrc);
        float fi = __shfl_sync(FULL, ai[k & 3], fsrc);
        if (i != k) {
            #pragma unroll
            for (int m = 0; m < 4; m++) {
                ar[m] -= fr*gr[m] - fi*gi[m];
                ai[m] -= fr*gi[m] + fi*gr[m];
            }
        }
    }

    float tr_r = 0.f, tr_i = 0.f;
    if (q == ((8 + i) >> 2)) {
        int m = (8 + i) & 3;
        tr_r = ar[m]; tr_i = ai[m];
    }
    #pragma unroll
    for (int o = 16; o; o >>= 1) {
        tr_r += __shfl_xor_sync(FULL, tr_r, o);
        tr_i += __shfl_xor_sync(FULL, tr_i, o);
    }
    tr_r += 1e-15f;

    float sr = 0.f, si = 0.f;
    if (q >= 2) {
        #pragma unroll
        for (int m = 0; m < 4; m++) {
            int c = (q - 2)*4 + m;
            float uu = u_sm[w][c];
            sr += ar[m]*uu; si += ai[m]*uu;
        }
    }
    sr += __shfl_xor_sync(FULL, sr, 1); si += __shfl_xor_sync(FULL, si, 1);
    sr += __shfl_xor_sync(FULL, sr, 2); si += __shfl_xor_sync(FULL, si, 2);
    if (q == 0) {
        float dd = 1.f / (tr_r*tr_r + tr_i*tr_i);
        float wr = (sr*tr_r + si*tr_i)*dd;
        float wi = (si*tr_r - sr*tr_i)*dd;
        g_ws[(size_t)bf*8 + i] = make_float2(wr, wi);
    }
}

// ---------------- beamforming -> output (B,T,F,2) ----------------
#define TCH 8
__global__ __launch_bounds__(288) void k_beam(const float* __restrict__ dr,
                                              const float* __restrict__ di,
                                              float2* __restrict__ out) {
    int blk = blockIdx.x;
    int b  = blk / (Tn / TCH);
    int t0 = (blk % (Tn / TCH)) * TCH;
    int f = threadIdx.x;
    if (f >= Fn) return;

    float2 wv[8];
    const float2* wp = g_ws + ((size_t)(b*Fn + f))*8;
    #pragma unroll
    for (int c = 0; c < 8; c++) wv[c] = wp[c];

    #pragma unroll
    for (int tt = 0; tt < TCH; tt++) {
        int t = t0 + tt;
        size_t base = ((size_t)(b*Tn + t))*Cn*Fn + f;
        float accr = 0.f, acci = 0.f;
        #pragma unroll
        for (int c = 0; c < 8; c++) {
            float xr = dr[base + (size_t)c*Fn];
            float xi = di[base + (size_t)c*Fn];
            accr += wv[c].x*xr + wv[c].y*xi;
            acci += wv[c].x*xi - wv[c].y*xr;
        }
        out[(size_t)(b*Tn + t)*Fn + f] = make_float2(accr, acci);
    }
}

// ---------------- launcher ----------------
extern "C" void kernel_launch(void* const* d_in, const int* in_sizes, int n_in,
                              void* d_out, int out_size) {
    const float* dr    = (const float*)d_in[0];
    const float* di    = (const float*)d_in[1];
    const float* ms    = (const float*)d_in[2];
    const float* mn    = (const float*)d_in[3];
    const float* mlp_w = (const float*)d_in[4];
    const float* mlp_b = (const float*)d_in[5];
    const float* gvw   = (const float*)d_in[6];
    const float* gvb   = (const float*)d_in[7];
    (void)in_sizes; (void)n_in; (void)out_size;

    static bool attr_set = false;
    if (!attr_set) {
        cudaFuncSetAttribute(k_psd_part, cudaFuncAttributeMaxDynamicSharedMemorySize,
                             (int)PSD_SMEM_BYTES);
        attr_set = true;
    }

    k_psd_part<<<dim3((Fn + FT - 1)/FT, TS, Bn), 256, PSD_SMEM_BYTES>>>(dr, di, ms, mn);
    k_psd_final<<<257, 288>>>();
    k_att<<<Bn*Cn, An>>>(mlp_w, mlp_b, gvw, gvb);
    k_mvdr<<<257, 256>>>();
    k_beam<<<Bn*(Tn/TCH), 288>>>(dr, di, (float2*)d_out);
}